// round 8
// baseline (speedup 1.0000x reference)
#include <cuda_runtime.h>
#include <cuda_bf16.h>

// ChannelPruner: out[b,o,h,w] = sum_c w[o,c] * x[b,c,h,w]
// x: (32, 256, 56, 56) fp32; w: (256,256,1,1) fp32, sparse rows discovered at
// runtime (correct for ANY w).
//
// R8 = R7 (fused, 8192 one-plane blocks, 256 thr, MLP-4, 32 regs / occ ~79%)
// with ONE isolated change: __stwt (write-through, no L2 allocation) on the
// output stores. The 103 MB write stream then never occupies L2, so the hot
// 77 MB of x becomes fully L2-resident across graph replays and DRAM reads
// drop to ~0 -> DRAM is a near-pure write stream.

#define N_CH   256
#define BATCH  32
#define HW4    784                    // (56*56)/4 float4 per plane
#define NPLANE (BATCH * N_CH)         // 8192 blocks

__global__ __launch_bounds__(256, 8) void prune_fused(const float4* __restrict__ x,
                                                      const float*  __restrict__ w,
                                                      float4* __restrict__ out) {
    __shared__ int   s_cols[N_CH];
    __shared__ float s_vals[N_CH];
    __shared__ int   s_warp_off[9];

    const int tid  = threadIdx.x;
    const int lane = tid & 31;
    const int wid  = tid >> 5;

    const int bo = blockIdx.x;        // plane index b*256 + o
    const int o  = bo & (N_CH - 1);

    // ---- prologue: deterministic compaction of w row o ----
    const float wv = __ldg(&w[o * N_CH + tid]);
    const unsigned mask = __ballot_sync(0xffffffffu, wv != 0.0f);
    if (lane == 0) s_warp_off[wid + 1] = __popc(mask);
    __syncthreads();
    if (tid == 0) {
        int acc = 0;
        s_warp_off[0] = 0;
#pragma unroll
        for (int i = 0; i < 8; i++) { acc += s_warp_off[i + 1]; s_warp_off[i + 1] = acc; }
    }
    __syncthreads();
    if (wv != 0.0f) {
        const int pos = s_warp_off[wid] + __popc(mask & ((1u << lane) - 1u));
        s_cols[pos] = tid;
        s_vals[pos] = wv;
    }
    __syncthreads();

    const int nnz = s_warp_off[8];

    // ---- body: 4 float4 outputs per thread, idx = tid + k*256 ----
    float4 z = make_float4(0.f, 0.f, 0.f, 0.f);
    float4 a0 = z, a1 = z, a2 = z, a3 = z;

    const float4* xb = x + (size_t)(bo >> 8) * (N_CH * HW4);   // batch base
    const bool tail = tid < (HW4 - 768);                        // tid < 16

    for (int j = 0; j < nnz; j++) {
        const int   c = s_cols[j];
        const float v = s_vals[j];
        const float4* xc = xb + (size_t)c * HW4 + tid;
        // 4 independent LDG.128 (MLP=4) before any FMA
        const float4 r0 = __ldg(xc);
        const float4 r1 = __ldg(xc + 256);
        const float4 r2 = __ldg(xc + 512);
        float4 r3 = z;
        if (tail) r3 = __ldg(xc + 768);

        a0.x += v * r0.x; a0.y += v * r0.y; a0.z += v * r0.z; a0.w += v * r0.w;
        a1.x += v * r1.x; a1.y += v * r1.y; a1.z += v * r1.z; a1.w += v * r1.w;
        a2.x += v * r2.x; a2.y += v * r2.y; a2.z += v * r2.z; a2.w += v * r2.w;
        if (tail) {
            a3.x += v * r3.x; a3.y += v * r3.y; a3.z += v * r3.z; a3.w += v * r3.w;
        }
    }

    // write-through stores: bypass L2 allocation so x stays L2-resident
    float4* ob = out + (size_t)bo * HW4 + tid;
    __stwt(ob,       a0);
    __stwt(ob + 256, a1);
    __stwt(ob + 512, a2);
    if (tail) __stwt(ob + 768, a3);
}

extern "C" void kernel_launch(void* const* d_in, const int* in_sizes, int n_in,
                              void* d_out, int out_size) {
    const float4* x = (const float4*)d_in[0];
    const float*  w = (const float*)d_in[1];
    float4* out = (float4*)d_out;

    prune_fused<<<NPLANE, 256>>>(x, w, out);
}